// round 7
// baseline (speedup 1.0000x reference)
#include <cuda_runtime.h>
#include <cuda_fp16.h>
#include <cstdint>

#define DO 128
#define HD 256
#define TILE 64

// ---------------- device-global scratch ----------------
__device__ __align__(16) __half g_Bh[2][DO * 128];     // fp16(Wf^T) [type][n*K + k]
__device__ float g_sum[2 * DO];
__device__ float g_sumsq[2 * DO];
__device__ float g_scale[2 * DO];
__device__ float g_shift[2 * DO];
__device__ __align__(16) __half g_H[128000000ULL];     // h fp16 (1e6 rows x 128)

// ---------------- PTX helpers ----------------
__device__ __forceinline__ uint32_t smem_u32(const void* p) {
    uint32_t a;
    asm("{ .reg .u64 t; cvta.to.shared.u64 t, %1; cvt.u32.u64 %0, t; }" : "=r"(a) : "l"(p));
    return a;
}
__device__ __forceinline__ void ldsm4(uint32_t* r, uint32_t addr) {
    asm volatile("ldmatrix.sync.aligned.m8n8.x4.shared.b16 {%0,%1,%2,%3}, [%4];"
        : "=r"(r[0]), "=r"(r[1]), "=r"(r[2]), "=r"(r[3]) : "r"(addr));
}
__device__ __forceinline__ void mmah(float* c, const uint32_t* a, const uint32_t* b) {
    asm volatile("mma.sync.aligned.m16n8k16.row.col.f32.f16.f16.f32 "
        "{%0,%1,%2,%3}, {%4,%5,%6,%7}, {%8,%9}, {%0,%1,%2,%3};"
        : "+f"(c[0]), "+f"(c[1]), "+f"(c[2]), "+f"(c[3])
        : "r"(a[0]), "r"(a[1]), "r"(a[2]), "r"(a[3]), "r"(b[0]), "r"(b[1]));
}
__device__ __forceinline__ uint32_t pkh(float lo, float hi) {
    uint32_t r;
    asm("cvt.rn.f16x2.f32 %0, %1, %2;" : "=r"(r) : "f"(hi), "f"(lo));
    return r;
}
__device__ __forceinline__ float hres(float a) {   // a - fp16(a)
    return a - __half2float(__float2half_rn(a));
}
__device__ __forceinline__ void cp16(uint32_t dst, const float* src, bool v) {
    int sz = v ? 16 : 0;
    asm volatile("cp.async.cg.shared.global [%0], [%1], 16, %2;"
                 :: "r"(dst), "l"(src), "r"(sz) : "memory");
}
#define CP_COMMIT() asm volatile("cp.async.commit_group;" ::: "memory")
#define CP_WAIT0()  asm volatile("cp.async.wait_group 0;" ::: "memory")

// ---------------- fold Wf = W1@W2 -> fp16(Wf^T); bias cancels in BN ----------------
__global__ void fold_kernel(const float* __restrict__ W1, const float* __restrict__ W2,
                            int K, int type) {
    int n = blockIdx.x;
    int k = threadIdx.x;
    if (type == 0 && n == 0) {        // fused stat zeroing (completes before gemm launch)
        g_sum[k] = 0.f;   g_sum[k + 128] = 0.f;
        g_sumsq[k] = 0.f; g_sumsq[k + 128] = 0.f;
    }
    if (k < K) {
        const float* w1 = W1 + (size_t)k * HD;
        float acc = 0.f;
        #pragma unroll 8
        for (int h = 0; h < HD; h++) acc = fmaf(w1[h], W2[h * DO + n], acc);
        g_Bh[type][n * K + k] = __float2half_rn(acc);
    }
}

// ---------------- pass 1: GEMM (2-term fp16), h -> g_H, column stats ----------------
// TILE=64 rows; 8 warps as 4(M) x 2(N); warp = 16 rows x 64 cols; 3 CTAs/SM.
template<int K, int TYPE>
__global__ __launch_bounds__(256, 3)
void gemm1_kernel(const float* __restrict__ X, __half* __restrict__ H, int N, int ntiles) {
    constexpr int NCH  = K / 64;
    constexpr int STR2 = K * 2 + 16;                 // B row stride (bytes)
    constexpr int ABUF = TILE * 256;                 // 16 KB per A buffer
    constexpr int SM_B    = 2 * ABUF;                // 32 KB
    constexpr int SM_STAT = SM_B + 128 * STR2;

    extern __shared__ char smc[];
    const uint32_t sb = smem_u32(smc);
    float* ssum = (float*)(smc + SM_STAT);
    float* ssq  = (float*)(smc + SM_STAT + 512);

    const int tid  = threadIdx.x;
    const int lane = tid & 31;
    const int wid  = tid >> 5;
    const int wm   = wid >> 1;                       // 0..3
    const int wn   = wid & 1;                        // 0..1
    const int jj   = lane & 3;
    const int rA   = wm * 16 + (lane >> 2);          // rows rA, rA+8 of tile
    const uint32_t sw0 = (uint32_t)((lane >> 2) << 4);
    const uint32_t sw1 = sw0 ^ 128u;

    // B -> smem once
    for (int i = tid; i < 128 * (K / 8); i += 256) {
        int n = i / (K / 8), g = i % (K / 8);
        *(uint4*)(smc + SM_B + n * STR2 + g * 16) = *(const uint4*)&g_Bh[TYPE][n * K + g * 8];
    }
    if (tid < 128) { ssum[tid] = 0.f; ssq[tid] = 0.f; }
    __syncthreads();

    const uint32_t bb4 = (uint32_t)((wn * 64 + (lane & 7) + ((lane >> 4) & 1) * 8) * STR2
                                    + ((lane >> 3) & 1) * 16);

    auto prefetch = [&](int tile, int c, int buf) {
        const uint32_t ab = sb + buf * ABUF;
        const int koff = c * 64;
        #pragma unroll
        for (int r4 = 0; r4 < 4; r4++) {
            int i   = tid + r4 * 256;
            int row = i >> 4;                        // 0..63
            int cb  = (i & 15) << 4;
            int grow = tile * TILE + row;
            bool v = grow < N;
            const float* src = v ? (X + (size_t)grow * K + koff + (cb >> 2)) : X;
            cp16(ab + (uint32_t)(row * 256) + ((uint32_t)cb ^ (uint32_t)((row & 15) << 4)), src, v);
        }
    };

    int tile0 = blockIdx.x;
    if (tile0 < ntiles) prefetch(tile0, 0, 0);
    CP_COMMIT();
    int buf = 0;

    for (int tile = tile0; tile < ntiles; tile += gridDim.x) {
        float acc[8][4];
        #pragma unroll
        for (int nt = 0; nt < 8; nt++)
            #pragma unroll
            for (int j = 0; j < 4; j++) acc[nt][j] = 0.f;

        #pragma unroll
        for (int c = 0; c < NCH; c++) {
            CP_WAIT0();
            __syncthreads();
            {
                int nc = c + 1, nt2 = tile;
                if (nc == NCH) { nc = 0; nt2 = tile + gridDim.x; }
                if (nt2 < ntiles) prefetch(nt2, nc, buf ^ 1);
                CP_COMMIT();
            }
            const int abuf = buf * ABUF;
            #pragma unroll
            for (int ks = 0; ks < 4; ks++) {
                const uint32_t cb = (uint32_t)(ks * 64 + jj * 8);
                float2 x00 = *(const float2*)(smc + abuf + rA * 256 + (cb ^ sw0));
                float2 x10 = *(const float2*)(smc + abuf + (rA + 8) * 256 + (cb ^ sw1));
                float2 x01 = *(const float2*)(smc + abuf + rA * 256 + ((cb + 32) ^ sw0));
                float2 x11 = *(const float2*)(smc + abuf + (rA + 8) * 256 + ((cb + 32) ^ sw1));

                uint32_t AH[4], AL[4];
                AH[0] = pkh(x00.x, x00.y); AL[0] = pkh(hres(x00.x), hres(x00.y));
                AH[1] = pkh(x10.x, x10.y); AL[1] = pkh(hres(x10.x), hres(x10.y));
                AH[2] = pkh(x01.x, x01.y); AL[2] = pkh(hres(x01.x), hres(x01.y));
                AH[3] = pkh(x11.x, x11.y); AL[3] = pkh(hres(x11.x), hres(x11.y));

                const uint32_t bbase = sb + SM_B + bb4 + (uint32_t)((c * 4 + ks) * 32);
                uint32_t bh[4][4];
                #pragma unroll
                for (int p = 0; p < 4; p++) ldsm4(bh[p], bbase + (uint32_t)(p * 16 * STR2));
                #pragma unroll
                for (int p = 0; p < 4; p++) {
                    mmah(acc[2 * p],     AH, &bh[p][0]);
                    mmah(acc[2 * p + 1], AH, &bh[p][2]);
                }
                #pragma unroll
                for (int p = 0; p < 4; p++) {
                    mmah(acc[2 * p],     AL, &bh[p][0]);
                    mmah(acc[2 * p + 1], AL, &bh[p][2]);
                }
            }
            buf ^= 1;
        }

        // ---- epilogue: stage fp16 h in consumed A buffer, then coalesced write + stats ----
        __syncthreads();                              // A rows shared by both wn warps
        const int stb = (buf ^ 1) * ABUF;
        {
            const uint32_t swr = (uint32_t)((rA & 7) << 4);
            #pragma unroll
            for (int nt = 0; nt < 8; nt++) {
                uint32_t c2 = (uint32_t)(wn * 128 + nt * 16 + jj * 4);
                *(uint32_t*)(smc + stb + rA * 256 + ((c2) ^ swr))       = pkh(acc[nt][0], acc[nt][1]);
                *(uint32_t*)(smc + stb + (rA + 8) * 256 + ((c2) ^ swr)) = pkh(acc[nt][2], acc[nt][3]);
            }
        }
        __syncwarp();
        float s8[8], q8[8];
        #pragma unroll
        for (int k = 0; k < 8; k++) { s8[k] = 0.f; q8[k] = 0.f; }
        const uint32_t gb = (uint32_t)(wn * 128 + (lane & 7) * 16);
        #pragma unroll
        for (int i = 0; i < 4; i++) {
            int row = wm * 16 + i * 4 + (lane >> 3);
            uint4 v = *(const uint4*)(smc + stb + row * 256 + (gb ^ (uint32_t)((row & 7) << 4)));
            const __half2* hv = (const __half2*)&v;
            #pragma unroll
            for (int k = 0; k < 4; k++) {
                float2 f = __half22float2(hv[k]);
                s8[2 * k]     += f.x;  q8[2 * k]     = fmaf(f.x, f.x, q8[2 * k]);
                s8[2 * k + 1] += f.y;  q8[2 * k + 1] = fmaf(f.y, f.y, q8[2 * k + 1]);
            }
            int grow = tile * TILE + row;
            if (grow < N)
                *(uint4*)(H + (size_t)grow * DO + wn * 64 + (lane & 7) * 8) = v;
        }
        // reduce stats over lanes sharing (lane&7), flush to per-CTA smem
        #pragma unroll
        for (int k = 0; k < 8; k++) {
            s8[k] += __shfl_xor_sync(0xFFFFFFFFu, s8[k], 8);
            s8[k] += __shfl_xor_sync(0xFFFFFFFFu, s8[k], 16);
            q8[k] += __shfl_xor_sync(0xFFFFFFFFu, q8[k], 8);
            q8[k] += __shfl_xor_sync(0xFFFFFFFFu, q8[k], 16);
        }
        if (lane < 8) {
            int col = wn * 64 + lane * 8;
            #pragma unroll
            for (int k = 0; k < 8; k++) {
                atomicAdd(&ssum[col + k], s8[k]);
                atomicAdd(&ssq[col + k],  q8[k]);
            }
        }
    }

    __syncthreads();
    if (tid < 128) {
        atomicAdd(&g_sum[TYPE * DO + tid],   ssum[tid]);
        atomicAdd(&g_sumsq[TYPE * DO + tid], ssq[tid]);
    }
}

// ---------------- finalize: fold BN + gamma/beta into affine ----------------
__global__ void finalize_kernel(const float* __restrict__ gu, const float* __restrict__ bu,
                                const float* __restrict__ gi, const float* __restrict__ bi,
                                float invNu, float invNi) {
    int t = threadIdx.x;
    int type = t >> 7, col = t & 127;
    float invN = type ? invNi : invNu;
    float mean = g_sum[t] * invN;
    float var  = g_sumsq[t] * invN - mean * mean;
    float inv  = rsqrtf(var + 1e-5f);
    float gm = type ? gi[col] : gu[col];
    float bt = type ? bi[col] : bu[col];
    g_scale[t] = inv * gm;
    g_shift[t] = bt - mean * inv * gm;
}

// ---------------- pass 2: normalize + LeakyReLU, 16 elems/thread (MLP=2) ----------------
__global__ void norm_kernel(const __half* __restrict__ H, float* __restrict__ out,
                            long long userElems, long long total16) {
    __shared__ float sc[256], sh[256];
    int t = threadIdx.x;
    sc[t] = g_scale[t];
    sh[t] = g_shift[t];
    __syncthreads();

    long long i16 = (long long)blockIdx.x * 256 + t;
    if (i16 >= total16) return;
    long long i = i16 * 16;
    int base = (i < userElems) ? 0 : 128;
    int col  = (int)(i & 127);           // 16-aligned; row width 128 -> no straddle

    uint4 hv0 = __ldcs((const uint4*)(H + i));
    uint4 hv1 = __ldcs((const uint4*)(H + i + 8));
    const __half2* h2a = (const __half2*)&hv0;
    const __half2* h2b = (const __half2*)&hv1;
    float r[16];
    #pragma unroll
    for (int k = 0; k < 4; k++) {
        float2 fa = __half22float2(h2a[k]);
        float2 fb = __half22float2(h2b[k]);
        r[2 * k] = fa.x; r[2 * k + 1] = fa.y;
        r[8 + 2 * k] = fb.x; r[9 + 2 * k] = fb.y;
    }
    #pragma unroll
    for (int k = 0; k < 16; k++) {
        float h = fmaf(r[k], sc[base + col + k], sh[base + col + k]);
        r[k] = (h >= 0.f) ? h : 0.01f * h;
    }
    __stcs((float4*)(out + i),      make_float4(r[0],  r[1],  r[2],  r[3]));
    __stcs((float4*)(out + i + 4),  make_float4(r[4],  r[5],  r[6],  r[7]));
    __stcs((float4*)(out + i + 8),  make_float4(r[8],  r[9],  r[10], r[11]));
    __stcs((float4*)(out + i + 12), make_float4(r[12], r[13], r[14], r[15]));
}

// ---------------- launch ----------------
extern "C" void kernel_launch(void* const* d_in, const int* in_sizes, int n_in,
                              void* d_out, int out_size) {
    const float* x_user  = (const float*)d_in[0];
    const float* x_item  = (const float*)d_in[1];
    const float* W1_user = (const float*)d_in[2];
    const float* W1_item = (const float*)d_in[4];
    const float* W2_user = (const float*)d_in[6];
    const float* W2_item = (const float*)d_in[8];
    const float* g_user  = (const float*)d_in[10];
    const float* be_user = (const float*)d_in[11];
    const float* g_item  = (const float*)d_in[12];
    const float* be_item = (const float*)d_in[13];

    const int Nu = in_sizes[0] / 64;
    const int Ni = in_sizes[1] / 128;
    float* out = (float*)d_out;

    __half* hbuf = nullptr;
    cudaGetSymbolAddress((void**)&hbuf, g_H);

    constexpr int SM_U = 32768 + 128 * (64 * 2 + 16) + 1024;    // 52224
    constexpr int SM_I = 32768 + 128 * (128 * 2 + 16) + 1024;   // 68608
    cudaFuncSetAttribute(gemm1_kernel<64, 0>,  cudaFuncAttributeMaxDynamicSharedMemorySize, SM_U);
    cudaFuncSetAttribute(gemm1_kernel<128, 1>, cudaFuncAttributeMaxDynamicSharedMemorySize, SM_I);

    fold_kernel<<<DO, 128>>>(W1_user, W2_user, 64, 0);
    fold_kernel<<<DO, 128>>>(W1_item, W2_item, 128, 1);

    const int tiles_u = (Nu + TILE - 1) / TILE;
    const int tiles_i = (Ni + TILE - 1) / TILE;
    const int GRID = 444;   // 3 CTAs x 148 SMs

    gemm1_kernel<64, 0><<<(tiles_u < GRID ? tiles_u : GRID), 256, SM_U>>>(x_user, hbuf, Nu, tiles_u);
    gemm1_kernel<128, 1><<<(tiles_i < GRID ? tiles_i : GRID), 256, SM_I>>>(x_item, hbuf + (size_t)Nu * DO, Ni, tiles_i);

    finalize_kernel<<<1, 256>>>(g_user, be_user, g_item, be_item, 1.0f / (float)Nu, 1.0f / (float)Ni);

    long long total   = ((long long)Nu + (long long)Ni) * DO;
    long long total16 = total / 16;
    unsigned grid = (unsigned)((total16 + 255) / 256);
    norm_kernel<<<grid, 256>>>(hbuf, out, (long long)Nu * DO, total16);
}

// round 8
// speedup vs baseline: 1.5302x; 1.5302x over previous
#include <cuda_runtime.h>
#include <cuda_fp16.h>
#include <cstdint>

#define DO 128
#define HD 256

// ---------------- device-global scratch ----------------
__device__ __align__(16) __half g_Bh[2][DO * 128];     // fp16(Wf^T) [type][n*K + k]
__device__ float g_sum[2 * DO];
__device__ float g_sumsq[2 * DO];
__device__ float g_scale[2 * DO];
__device__ float g_shift[2 * DO];
__device__ __align__(16) __half g_H[128000000ULL];     // h fp16 (1e6 rows x 128)

// ---------------- PTX helpers ----------------
__device__ __forceinline__ uint32_t smem_u32(const void* p) {
    uint32_t a;
    asm("{ .reg .u64 t; cvta.to.shared.u64 t, %1; cvt.u32.u64 %0, t; }" : "=r"(a) : "l"(p));
    return a;
}
__device__ __forceinline__ void ldsm4(uint32_t* r, uint32_t addr) {
    asm volatile("ldmatrix.sync.aligned.m8n8.x4.shared.b16 {%0,%1,%2,%3}, [%4];"
        : "=r"(r[0]), "=r"(r[1]), "=r"(r[2]), "=r"(r[3]) : "r"(addr));
}
__device__ __forceinline__ void mmah(float* c, const uint32_t* a, const uint32_t* b) {
    asm volatile("mma.sync.aligned.m16n8k16.row.col.f32.f16.f16.f32 "
        "{%0,%1,%2,%3}, {%4,%5,%6,%7}, {%8,%9}, {%0,%1,%2,%3};"
        : "+f"(c[0]), "+f"(c[1]), "+f"(c[2]), "+f"(c[3])
        : "r"(a[0]), "r"(a[1]), "r"(a[2]), "r"(a[3]), "r"(b[0]), "r"(b[1]));
}
// pack (lo, hi) -> f16x2 with lo in low half
__device__ __forceinline__ uint32_t pkh(float lo, float hi) {
    uint32_t r;
    asm("cvt.rn.f16x2.f32 %0, %1, %2;" : "=r"(r) : "f"(hi), "f"(lo));
    return r;
}
__device__ __forceinline__ void cp16(uint32_t dst, const float* src, bool v) {
    int sz = v ? 16 : 0;
    asm volatile("cp.async.cg.shared.global [%0], [%1], 16, %2;"
                 :: "r"(dst), "l"(src), "r"(sz) : "memory");
}
#define CP_COMMIT() asm volatile("cp.async.commit_group;" ::: "memory")
#define CP_WAIT0()  asm volatile("cp.async.wait_group 0;" ::: "memory")

// ---------------- fold Wf = W1@W2 -> fp16(Wf^T); bias cancels in BN ----------------
__global__ void fold_kernel(const float* __restrict__ W1, const float* __restrict__ W2,
                            int K, int type) {
    int n = blockIdx.x;
    int k = threadIdx.x;
    if (type == 0 && n == 0) {        // fused stat zeroing
        g_sum[k] = 0.f;   g_sum[k + 128] = 0.f;
        g_sumsq[k] = 0.f; g_sumsq[k + 128] = 0.f;
    }
    if (k < K) {
        const float* w1 = W1 + (size_t)k * HD;
        float acc = 0.f;
        #pragma unroll 8
        for (int h = 0; h < HD; h++) acc = fmaf(w1[h], W2[h * DO + n], acc);
        g_Bh[type][n * K + k] = __float2half_rn(acc);
    }
}

// ---------------- pass 1: GEMM (single-term fp16), h -> g_H, column stats ----------------
// TILE=128 rows; 8 warps, warp = 16 rows x 128 cols; 2 CTAs/SM.
template<int K, int TYPE>
__global__ __launch_bounds__(256, 2)
void gemm1_kernel(const float* __restrict__ X, __half* __restrict__ H, int N, int ntiles) {
    constexpr int NCH  = K / 64;
    constexpr int STR2 = K * 2 + 16;                 // B row stride (bytes)
    constexpr int SM_B    = 65536;                   // after two 32KB A buffers
    constexpr int SM_STAT = SM_B + 128 * STR2;

    extern __shared__ char smc[];
    const uint32_t sb = smem_u32(smc);
    float* ssum = (float*)(smc + SM_STAT);
    float* ssq  = (float*)(smc + SM_STAT + 512);

    const int tid  = threadIdx.x;
    const int lane = tid & 31;
    const int wid  = tid >> 5;
    const int jj   = lane & 3;
    const int rA   = wid * 16 + (lane >> 2);         // warp-private rows rA, rA+8
    const uint32_t sw0 = (uint32_t)((lane >> 2) << 4);
    const uint32_t sw1 = sw0 ^ 128u;

    // B -> smem once
    for (int i = tid; i < 128 * (K / 8); i += 256) {
        int n = i / (K / 8), g = i % (K / 8);
        *(uint4*)(smc + SM_B + n * STR2 + g * 16) = *(const uint4*)&g_Bh[TYPE][n * K + g * 8];
    }
    if (tid < 128) { ssum[tid] = 0.f; ssq[tid] = 0.f; }
    __syncthreads();

    const uint32_t bb4 = (uint32_t)(((lane & 7) + ((lane >> 4) & 1) * 8) * STR2 + ((lane >> 3) & 1) * 16);

    float s8[8], q8[8];
    #pragma unroll
    for (int k = 0; k < 8; k++) { s8[k] = 0.f; q8[k] = 0.f; }

    auto prefetch = [&](int tile, int c, int buf) {
        const uint32_t ab = sb + buf * 32768;
        const int koff = c * 64;
        #pragma unroll
        for (int r8 = 0; r8 < 8; r8++) {
            int i   = tid + r8 * 256;
            int row = i >> 4;
            int cb  = (i & 15) << 4;
            int grow = (tile << 7) + row;
            bool v = grow < N;
            const float* src = v ? (X + (size_t)grow * K + koff + (cb >> 2)) : X;
            cp16(ab + (uint32_t)(row * 256) + ((uint32_t)cb ^ (uint32_t)((row & 15) << 4)), src, v);
        }
    };

    int tile0 = blockIdx.x;
    if (tile0 < ntiles) prefetch(tile0, 0, 0);
    CP_COMMIT();
    int buf = 0;

    for (int tile = tile0; tile < ntiles; tile += gridDim.x) {
        float acc[16][4];
        #pragma unroll
        for (int nt = 0; nt < 16; nt++)
            #pragma unroll
            for (int j = 0; j < 4; j++) acc[nt][j] = 0.f;

        #pragma unroll
        for (int c = 0; c < NCH; c++) {
            CP_WAIT0();
            __syncthreads();
            {
                int nc = c + 1, nt2 = tile;
                if (nc == NCH) { nc = 0; nt2 = tile + gridDim.x; }
                if (nt2 < ntiles) prefetch(nt2, nc, buf ^ 1);
                CP_COMMIT();
            }
            const int abuf = buf * 32768;
            #pragma unroll
            for (int ks = 0; ks < 4; ks++) {
                const uint32_t cb = (uint32_t)(ks * 64 + jj * 8);
                float2 x00 = *(const float2*)(smc + abuf + rA * 256 + (cb ^ sw0));
                float2 x10 = *(const float2*)(smc + abuf + (rA + 8) * 256 + (cb ^ sw1));
                float2 x01 = *(const float2*)(smc + abuf + rA * 256 + ((cb + 32) ^ sw0));
                float2 x11 = *(const float2*)(smc + abuf + (rA + 8) * 256 + ((cb + 32) ^ sw1));

                uint32_t AH[4];
                AH[0] = pkh(x00.x, x00.y);
                AH[1] = pkh(x10.x, x10.y);
                AH[2] = pkh(x01.x, x01.y);
                AH[3] = pkh(x11.x, x11.y);

                const uint32_t bbase = sb + SM_B + bb4 + (uint32_t)((c * 4 + ks) * 32);
                #pragma unroll
                for (int g = 0; g < 2; g++) {
                    uint32_t bh[4][4];
                    #pragma unroll
                    for (int p = 0; p < 4; p++)
                        ldsm4(bh[p], bbase + (uint32_t)((g * 4 + p) * 16 * STR2));
                    #pragma unroll
                    for (int p = 0; p < 4; p++) {
                        mmah(acc[2 * (g * 4 + p)],     AH, &bh[p][0]);
                        mmah(acc[2 * (g * 4 + p) + 1], AH, &bh[p][2]);
                    }
                }
            }
            buf ^= 1;
        }

        // ---- epilogue: warp-private staging in the just-consumed buffer ----
        const int stb = (buf ^ 1) * 32768;
        #pragma unroll
        for (int nt = 0; nt < 16; nt++) {
            uint32_t c2 = (uint32_t)(nt * 16 + jj * 4);
            *(uint32_t*)(smc + stb + rA * 256 + (c2 ^ sw0))       = pkh(acc[nt][0], acc[nt][1]);
            *(uint32_t*)(smc + stb + (rA + 8) * 256 + (c2 ^ sw1)) = pkh(acc[nt][2], acc[nt][3]);
        }
        __syncwarp();
        #pragma unroll
        for (int i = 0; i < 8; i++) {
            int rr = wid * 16 + (lane >> 4) + i * 2;
            uint32_t c2 = (uint32_t)((lane & 15) << 4);
            uint4 v = *(const uint4*)(smc + stb + rr * 256 + (c2 ^ (uint32_t)((rr & 15) << 4)));
            const __half2* hv = (const __half2*)&v;
            #pragma unroll
            for (int k = 0; k < 4; k++) {
                float2 f = __half22float2(hv[k]);
                s8[2 * k]     += f.x;  q8[2 * k]     = fmaf(f.x, f.x, q8[2 * k]);
                s8[2 * k + 1] += f.y;  q8[2 * k + 1] = fmaf(f.y, f.y, q8[2 * k + 1]);
            }
            int grow = (tile << 7) + rr;
            if (grow < N) *(uint4*)(H + (size_t)grow * DO + (lane & 15) * 8) = v;
        }
    }

    // ---- flush stats ----
    #pragma unroll
    for (int k = 0; k < 8; k++) {
        s8[k] += __shfl_down_sync(0xFFFFFFFFu, s8[k], 16);
        q8[k] += __shfl_down_sync(0xFFFFFFFFu, q8[k], 16);
    }
    if (lane < 16) {
        #pragma unroll
        for (int k = 0; k < 8; k++) {
            atomicAdd(&ssum[lane * 8 + k], s8[k]);
            atomicAdd(&ssq[lane * 8 + k],  q8[k]);
        }
    }
    __syncthreads();
    if (tid < 128) {
        atomicAdd(&g_sum[TYPE * DO + tid],   ssum[tid]);
        atomicAdd(&g_sumsq[TYPE * DO + tid], ssq[tid]);
    }
}

// ---------------- finalize: fold BN + gamma/beta into affine ----------------
__global__ void finalize_kernel(const float* __restrict__ gu, const float* __restrict__ bu,
                                const float* __restrict__ gi, const float* __restrict__ bi,
                                float invNu, float invNi) {
    int t = threadIdx.x;
    int type = t >> 7, col = t & 127;
    float invN = type ? invNi : invNu;
    float mean = g_sum[t] * invN;
    float var  = g_sumsq[t] * invN - mean * mean;
    float inv  = rsqrtf(var + 1e-5f);
    float gm = type ? gi[col] : gu[col];
    float bt = type ? bi[col] : bu[col];
    g_scale[t] = inv * gm;
    g_shift[t] = bt - mean * inv * gm;
}

// ---------------- pass 2: normalize + LeakyReLU, 8 elems/thread, streaming ----------------
__global__ void norm_kernel(const __half* __restrict__ H, float* __restrict__ out,
                            long long userElems, long long total8) {
    __shared__ float sc[256], sh[256];
    int t = threadIdx.x;
    sc[t] = g_scale[t];
    sh[t] = g_shift[t];
    __syncthreads();

    long long i8 = (long long)blockIdx.x * 256 + t;
    if (i8 >= total8) return;
    long long i = i8 * 8;
    int base = (i < userElems) ? 0 : 128;
    int col  = (int)(i & 127);           // 8-aligned; row width 128 -> no straddle

    uint4 hv = __ldcs((const uint4*)(H + i));
    const __half2* h2 = (const __half2*)&hv;
    float r[8];
    #pragma unroll
    for (int k = 0; k < 4; k++) {
        float2 f = __half22float2(h2[k]);
        r[2 * k] = f.x; r[2 * k + 1] = f.y;
    }
    #pragma unroll
    for (int k = 0; k < 8; k++) {
        float h = fmaf(r[k], sc[base + col + k], sh[base + col + k]);
        r[k] = (h >= 0.f) ? h : 0.01f * h;
    }
    __stcs((float4*)(out + i),     make_float4(r[0], r[1], r[2], r[3]));
    __stcs((float4*)(out + i + 4), make_float4(r[4], r[5], r[6], r[7]));
}

// ---------------- launch ----------------
extern "C" void kernel_launch(void* const* d_in, const int* in_sizes, int n_in,
                              void* d_out, int out_size) {
    const float* x_user  = (const float*)d_in[0];
    const float* x_item  = (const float*)d_in[1];
    const float* W1_user = (const float*)d_in[2];
    const float* W1_item = (const float*)d_in[4];
    const float* W2_user = (const float*)d_in[6];
    const float* W2_item = (const float*)d_in[8];
    const float* g_user  = (const float*)d_in[10];
    const float* be_user = (const float*)d_in[11];
    const float* g_item  = (const float*)d_in[12];
    const float* be_item = (const float*)d_in[13];

    const int Nu = in_sizes[0] / 64;
    const int Ni = in_sizes[1] / 128;
    float* out = (float*)d_out;

    __half* hbuf = nullptr;
    cudaGetSymbolAddress((void**)&hbuf, g_H);

    constexpr int SM_U = 65536 + 128 * (64 * 2 + 16) + 1024;    // 85 KB
    constexpr int SM_I = 65536 + 128 * (128 * 2 + 16) + 1024;   // 101 KB
    cudaFuncSetAttribute(gemm1_kernel<64, 0>,  cudaFuncAttributeMaxDynamicSharedMemorySize, SM_U);
    cudaFuncSetAttribute(gemm1_kernel<128, 1>, cudaFuncAttributeMaxDynamicSharedMemorySize, SM_I);

    fold_kernel<<<DO, 128>>>(W1_user, W2_user, 64, 0);
    fold_kernel<<<DO, 128>>>(W1_item, W2_item, 128, 1);

    const int tiles_u = (Nu + 127) / 128;
    const int tiles_i = (Ni + 127) / 128;
    const int GRID = 296;

    gemm1_kernel<64, 0><<<(tiles_u < GRID ? tiles_u : GRID), 256, SM_U>>>(x_user, hbuf, Nu, tiles_u);
    gemm1_kernel<128, 1><<<(tiles_i < GRID ? tiles_i : GRID), 256, SM_I>>>(x_item, hbuf + (size_t)Nu * DO, Ni, tiles_i);

    finalize_kernel<<<1, 256>>>(g_user, be_user, g_item, be_item, 1.0f / (float)Nu, 1.0f / (float)Ni);

    long long total  = ((long long)Nu + (long long)Ni) * DO;
    long long total8 = total / 8;
    unsigned grid = (unsigned)((total8 + 255) / 256);
    norm_kernel<<<grid, 256>>>(hbuf, out, (long long)Nu * DO, total8);
}